// round 3
// baseline (speedup 1.0000x reference)
#include <cuda_runtime.h>
#include <cuda_bf16.h>
#include <math.h>

// PCEN: m = EMA(x, S=0.5); out = (x / (eps+m)^alpha + delta)^r - delta^r
// x: [1024, 32768] fp32 row-major.
//
// Warp-shuffle chunked scan, zero shared memory:
//  - Lane owns 4 contiguous elements (float4); warp covers 128 contiguous
//    elements -> fully coalesced LDG.128/STG.128, no smem transpose.
//  - Cross-lane carry: decayed inclusive scan, decay w = 0.5^4 per lane.
//    w^16 = 2^-64 -> 4 Hillis-Steele steps (window 16) are exact to 2^-64.
//  - Next iteration's carry = shfl(scan, 31): the previous carry's
//    contribution decays by 0.5^128 = 0 in fp32 -> no serial carry chain.
//  - Each warp walks RUN=4096 contiguous elements (32 iters). Warps not at a
//    row start load a 64-element halo once (0.5^64 truncation, negligible).
//  - Pointwise: ex2(-alpha*lg2(eps+m)), sqrt.approx for r==0.5: 3 MUFU/elem.

#define ROW   32768
#define ITER  32
#define RUN   (ITER * 128)      // 4096 elements per warp
#define NTHREADS 256

__device__ __forceinline__ float fast_lg2(float v) {
    float r_; asm("lg2.approx.f32 %0, %1;" : "=f"(r_) : "f"(v)); return r_;
}
__device__ __forceinline__ float fast_ex2(float v) {
    float r_; asm("ex2.approx.f32 %0, %1;" : "=f"(r_) : "f"(v)); return r_;
}
__device__ __forceinline__ float fast_sqrt(float v) {
    float r_; asm("sqrt.approx.f32 %0, %1;" : "=f"(r_) : "f"(v)); return r_;
}

__device__ __forceinline__ float pcen_pt(float xv, float m, float na,
                                         float r, float delta, float dr,
                                         bool rhalf) {
    float l = fast_lg2(m + 1e-6f);             // MUFU.LG2
    float p = fast_ex2(na * l);                // MUFU.EX2 -> (eps+m)^(-alpha)
    float u = fmaf(xv, p, delta);              // u >= delta > 0
    float s = rhalf ? fast_sqrt(u) : fast_ex2(r * fast_lg2(u));
    return s - dr;
}

__global__ void __launch_bounds__(NTHREADS) pcen_kernel(
    const float* __restrict__ x,
    const float* __restrict__ p_alpha,
    const float* __restrict__ p_r,
    const float* __restrict__ p_delta,
    float* __restrict__ out,
    int total)
{
    const int warp = (blockIdx.x * NTHREADS + threadIdx.x) >> 5;
    const int lane = threadIdx.x & 31;
    const long long base = (long long)warp * RUN;
    if (base >= total) return;

    const float w1 = 0x1p-4f, w2 = 0x1p-8f, w4 = 0x1p-16f, w8 = 0x1p-32f;
    // 2^(-4*lane): exact power of two via exponent bits (min exp = 127-124 = 3)
    const float wpow = __int_as_float((127 - 4 * lane) << 23);

    // ---- halo: EMA over the 64 elements preceding base (if not row start) ----
    float carry = 0.f;
    if (base & (ROW - 1)) {
        float hb = 0.f;
        if (lane < 16) {
            float4 h = *(const float4*)(x + base - 64 + 4 * lane);
            float m = 0.5f * h.x;
            m = 0.5f * (m + h.y);
            m = 0.5f * (m + h.z);
            m = 0.5f * (m + h.w);
            hb = m;
        }
        float s = hb, u;
        u = __shfl_up_sync(~0u, s, 1); if (lane >= 1) s = fmaf(u, w1, s);
        u = __shfl_up_sync(~0u, s, 2); if (lane >= 2) s = fmaf(u, w2, s);
        u = __shfl_up_sync(~0u, s, 4); if (lane >= 4) s = fmaf(u, w4, s);
        u = __shfl_up_sync(~0u, s, 8); if (lane >= 8) s = fmaf(u, w8, s);
        carry = __shfl_sync(~0u, s, 15);       // EMA of the 64-elem halo
    }

    const float alpha = __ldg(p_alpha);
    const float r     = __ldg(p_r);
    const float delta = __ldg(p_delta);
    const float na    = -alpha;
    const float dr    = fast_ex2(r * fast_lg2(delta));
    const bool rhalf  = (r == 0.5f);

    const float4* gin  = (const float4*)(x   + base) + lane;
    float4*       gout = (float4*)      (out + base) + lane;

    #pragma unroll 4
    for (int it = 0; it < ITER; ++it) {
        float4 v = gin[it * 32];

        // local zero-start EMA of this lane's 4 elements (keep intermediates)
        float lm1 = 0.5f * v.x;
        float lm2 = 0.5f * (lm1 + v.y);
        float lm3 = 0.5f * (lm2 + v.z);
        float lm4 = 0.5f * (lm3 + v.w);

        // decayed inclusive scan across lanes (window 16 is exact to 2^-64)
        float s = lm4, u;
        u = __shfl_up_sync(~0u, s, 1); if (lane >= 1) s = fmaf(u, w1, s);
        u = __shfl_up_sync(~0u, s, 2); if (lane >= 2) s = fmaf(u, w2, s);
        u = __shfl_up_sync(~0u, s, 4); if (lane >= 4) s = fmaf(u, w4, s);
        u = __shfl_up_sync(~0u, s, 8); if (lane >= 8) s = fmaf(u, w8, s);

        float prev = __shfl_up_sync(~0u, s, 1);
        if (lane == 0) prev = 0.f;
        float E = fmaf(carry, wpow, prev);      // m entering this lane's chunk
        carry = __shfl_sync(~0u, s, 31);        // old carry decays by 0.5^128

        // per-element m: m_k = lm_k + E * 0.5^k
        float m1 = fmaf(E, 0.5f,    lm1);
        float m2 = fmaf(E, 0.25f,   lm2);
        float m3 = fmaf(E, 0.125f,  lm3);
        float m4 = fmaf(E, 0.0625f, lm4);

        float4 o;
        o.x = pcen_pt(v.x, m1, na, r, delta, dr, rhalf);
        o.y = pcen_pt(v.y, m2, na, r, delta, dr, rhalf);
        o.z = pcen_pt(v.z, m3, na, r, delta, dr, rhalf);
        o.w = pcen_pt(v.w, m4, na, r, delta, dr, rhalf);
        gout[it * 32] = o;
    }
}

extern "C" void kernel_launch(void* const* d_in, const int* in_sizes, int n_in,
                              void* d_out, int out_size) {
    (void)n_in; (void)out_size;
    const float* x     = (const float*)d_in[0];
    const float* alpha = (const float*)d_in[1];
    const float* r     = (const float*)d_in[2];
    const float* delta = (const float*)d_in[3];
    float* out = (float*)d_out;

    int total  = in_sizes[0];                 // 1024 * 32768 = 33554432
    int warps  = total / RUN;                 // 8192
    int blocks = warps / (NTHREADS / 32);     // 1024

    pcen_kernel<<<blocks, NTHREADS>>>(x, alpha, r, delta, out, total);
}